// round 15
// baseline (speedup 1.0000x reference)
#include <cuda_runtime.h>
#include <cuda_fp16.h>
#include <cstdint>

#define BB 8
#define SS 2048
#define DD 1024
#define MS (BB * SS)   // 16384
#define NTHR 512

// ---------------- scratch (device globals; no cudaMalloc allowed) ----------
__device__ __half g_xh  [(size_t)MS * DD];      // 32 MB  x fp16
__device__ __half g_wq16[(size_t)DD * DD];      //  2 MB  Wq fp16 (row-major)
__device__ __half g_wk16[(size_t)DD * DD];      //  2 MB  Wk fp16 (row-major)
__device__ __half g_wvt [(size_t)DD * DD];      //  2 MB  Wv^T fp16
__device__ __half g_mt  [(size_t)DD * DD];      //  2 MB  (Wk Wq^T)[c][d] fp16
__device__ __half g_th  [(size_t)MS * DD];      // 32 MB  t = x (Wq Wk^T)
__device__ __half g_vt  [(size_t)DD * MS];      // 32 MB  v^T: [e][b*2048+j]
__device__ __half g_w   [(size_t)BB * SS * SS]; // 64 MB  P = exp(s/32) fp16
__device__ float  g_c   [(size_t)MS];           // 64 KB  column sums

// ---------------- smem: 2 stages x (A 16KB + B 16KB) -----------------------
#define STAGE_B 32768
#define SMEM_BYTES (2 * STAGE_B)   // 65536

// ---------------- PTX helpers ----------------------------------------------
__device__ __forceinline__ uint32_t smem_u32(const void* p) {
    uint32_t a;
    asm("{ .reg .u64 t; cvta.to.shared.u64 t, %1; cvt.u32.u64 %0, t; }"
        : "=r"(a) : "l"(p));
    return a;
}
__device__ __forceinline__ void cpa16(uint32_t d, const void* s) {
    asm volatile("cp.async.cg.shared.global [%0], [%1], 16;"
                 :: "r"(d), "l"(s) : "memory");
}
#define CP_COMMIT() asm volatile("cp.async.commit_group;" ::: "memory")
#define CP_WAIT(n)  asm volatile("cp.async.wait_group %0;" :: "n"(n) : "memory")

__device__ __forceinline__ void ldsm_x4(uint32_t* r, uint32_t addr) {
    asm volatile("ldmatrix.sync.aligned.m8n8.x4.shared.b16 {%0,%1,%2,%3}, [%4];"
        : "=r"(r[0]), "=r"(r[1]), "=r"(r[2]), "=r"(r[3]) : "r"(addr));
}
__device__ __forceinline__ void mma16816(float* c, const uint32_t* a,
                                         const uint32_t* b) {
    asm volatile(
        "mma.sync.aligned.m16n8k16.row.col.f32.f16.f16.f32 "
        "{%0,%1,%2,%3}, {%4,%5,%6,%7}, {%8,%9}, {%0,%1,%2,%3};"
        : "+f"(c[0]), "+f"(c[1]), "+f"(c[2]), "+f"(c[3])
        : "r"(a[0]), "r"(a[1]), "r"(a[2]), "r"(a[3]), "r"(b[0]), "r"(b[1]));
}

// fill one stage: A/B tiles 128 rows x 64 fp16 (128B/row), XOR swizzle
// 512 threads: 2 cp.async per tile per thread.
__device__ __forceinline__ void fill_stage(
    uint32_t sbase, int stg, const __half* A, int lda,
    const __half* B, int ldb, int k0, int tid)
{
    const uint32_t sA = sbase + stg * STAGE_B;
    const uint32_t sB = sA + 16384;
#pragma unroll
    for (int i = 0; i < 2; i++) {
        const int id = tid + (i << 9);
        const int r = id >> 3;
        const int c = id & 7;
        const uint32_t sw = (uint32_t)r * 128 + (uint32_t)((c ^ (r & 7)) << 4);
        cpa16(sA + sw, A + (size_t)r * lda + k0 + c * 8);
        cpa16(sB + sw, B + (size_t)r * ldb + k0 + c * 8);
    }
    CP_COMMIT();
}

// ---------------------------------------------------------------------------
// 128x128 tile GEMM, 512 threads, warp tile 32x32 (4m x 4n warps).
// C[m][n] = f(scale * sum_k A[m][k]*B[n][k]); kelems multiple of 64 (>=128).
// MODE 0: fp16 scaled; MODE 1: fp32 scaled;
// MODE 2: fp16 exp(scaled), causal-zeroed; fused column sums into gsum.
// ---------------------------------------------------------------------------
template<int MODE>
__device__ __forceinline__ void gemm_fp16(
    const __half* __restrict__ A, int lda,
    const __half* __restrict__ B, int ldb,
    void* __restrict__ Cv, int ldc, int kelems, float scale,
    int ri0 = 0, int cj0 = 0, float* gsum = nullptr)
{
    extern __shared__ char sm[];
    const uint32_t sbase = smem_u32(sm);
    const int tid  = threadIdx.x;
    const int lane = tid & 31;
    const int wid  = tid >> 5;            // 0..15
    const int wm   = (wid & 3) * 32;      // 4 warps over m
    const int wn   = (wid >> 2) * 32;     // 4 warps over n

    const int ra = lane & 15;
    const int ca = (lane >> 4) * 16;
    const int rb = (lane & 7) + (lane >> 4) * 8;
    const int cb = ((lane >> 3) & 1) * 16;

    float acc[2][4][4] = {};

    const int nc = kelems >> 6;
    fill_stage(sbase, 0, A, lda, B, ldb, 0, tid);

    for (int ch = 0; ch < nc; ch++) {
        const int s = ch & 1;
        if (ch + 1 < nc) {
            fill_stage(sbase, s ^ 1, A, lda, B, ldb, (ch + 1) << 6, tid);
            CP_WAIT(1);
        } else {
            CP_WAIT(0);
        }
        __syncthreads();

        const uint32_t sA = sbase + s * STAGE_B;
        const uint32_t sB = sA + 16384;
#pragma unroll
        for (int kk = 0; kk < 4; kk++) {
            uint32_t a[2][4], b[2][4];
#pragma unroll
            for (int mt = 0; mt < 2; mt++) {
                const int r = wm + mt * 16 + ra;
                const int col = kk * 32 + ca;
                ldsm_x4(a[mt], sA + (uint32_t)r * 128 +
                               (uint32_t)((((col >> 4) ^ (r & 7))) << 4));
            }
#pragma unroll
            for (int np = 0; np < 2; np++) {
                const int r = wn + np * 16 + rb;
                const int col = kk * 32 + cb;
                ldsm_x4(b[np], sB + (uint32_t)r * 128 +
                               (uint32_t)((((col >> 4) ^ (r & 7))) << 4));
            }
#pragma unroll
            for (int mt = 0; mt < 2; mt++)
#pragma unroll
                for (int nt = 0; nt < 4; nt++)
                    mma16816(acc[mt][nt], a[mt], &b[nt >> 1][(nt & 1) * 2]);
        }
        __syncthreads();
    }

    // epilogue
    const int er = lane >> 2;
    const int ec = (lane & 3) * 2;

    float* csum = (float*)sm;          // stages dead after final barrier
    if (MODE == 2) {
        if (tid < 128) csum[tid] = 0.f;
        __syncthreads();
    }
    float cs[4][2] = {};               // per-(nt) column partials (MODE 2)

#pragma unroll
    for (int mt = 0; mt < 2; mt++)
#pragma unroll
        for (int nt = 0; nt < 4; nt++) {
            const int r = wm + mt * 16 + er;
            const int cn = wn + nt * 8 + ec;
            if (MODE == 0) {
                __half* C = (__half*)Cv;
                *(__half2*)(C + (size_t)r * ldc + cn) =
                    __floats2half2_rn(acc[mt][nt][0] * scale,
                                      acc[mt][nt][1] * scale);
                *(__half2*)(C + (size_t)(r + 8) * ldc + cn) =
                    __floats2half2_rn(acc[mt][nt][2] * scale,
                                      acc[mt][nt][3] * scale);
            } else if (MODE == 1) {
                float* C = (float*)Cv;
                *(float2*)(C + (size_t)r * ldc + cn) =
                    make_float2(acc[mt][nt][0] * scale, acc[mt][nt][1] * scale);
                *(float2*)(C + (size_t)(r + 8) * ldc + cn) =
                    make_float2(acc[mt][nt][2] * scale, acc[mt][nt][3] * scale);
            } else {
                __half* C = (__half*)Cv;
                const int i0 = ri0 + r, i1 = ri0 + r + 8;
                const int j0c = cj0 + cn, j1c = cj0 + cn + 1;
                float e00 = (i0 >= j0c) ? __expf(acc[mt][nt][0] * scale) : 0.f;
                float e01 = (i0 >= j1c) ? __expf(acc[mt][nt][1] * scale) : 0.f;
                float e10 = (i1 >= j0c) ? __expf(acc[mt][nt][2] * scale) : 0.f;
                float e11 = (i1 >= j1c) ? __expf(acc[mt][nt][3] * scale) : 0.f;
                *(__half2*)(C + (size_t)r * ldc + cn) = __floats2half2_rn(e00, e01);
                *(__half2*)(C + (size_t)(r + 8) * ldc + cn) = __floats2half2_rn(e10, e11);
                cs[nt][0] += e00 + e10;
                cs[nt][1] += e01 + e11;
            }
        }

    if (MODE == 2) {
#pragma unroll
        for (int nt = 0; nt < 4; nt++) {
#pragma unroll
            for (int off = 16; off >= 4; off >>= 1) {
                cs[nt][0] += __shfl_down_sync(0xffffffffu, cs[nt][0], off);
                cs[nt][1] += __shfl_down_sync(0xffffffffu, cs[nt][1], off);
            }
            if (lane < 4) {
                const int c0 = wn + nt * 8 + lane * 2;
                atomicAdd(&csum[c0],     cs[nt][0]);
                atomicAdd(&csum[c0 + 1], cs[nt][1]);
            }
        }
        __syncthreads();
        if (tid < 128) atomicAdd(&gsum[tid], csum[tid]);
    }
}

// ---------------------------------------------------------------------------
// Mt[c][d] = sum_e Wk[c][e] * Wq[d][e]
// ---------------------------------------------------------------------------
__global__ __launch_bounds__(NTHR, 2) void k_mt()
{
    gemm_fp16<0>(g_wk16 + (size_t)blockIdx.y * 128 * DD, DD,
                 g_wq16 + (size_t)blockIdx.x * 128 * DD, DD,
                 g_mt + (size_t)blockIdx.y * 128 * DD + blockIdx.x * 128, DD,
                 DD, 1.0f);
}

// ---------------------------------------------------------------------------
// Projections: t[i][c] = sum_d x[i][d] * Mt[c][d]  (tiles 0..1023)
//              vt[e][jg] = sum_d Wv^T[e][d] * x[jg][d]  (tiles 1024..2047)
// ---------------------------------------------------------------------------
__global__ __launch_bounds__(NTHR, 2) void k_proj()
{
    const int t = blockIdx.x;
    if (t < 1024) {
        const int my = t >> 3;
        const int nx = t & 7;
        gemm_fp16<0>(g_xh + (size_t)my * 128 * DD, DD,
                     g_mt + (size_t)nx * 128 * DD, DD,
                     g_th + (size_t)my * 128 * DD + nx * 128, DD,
                     DD, 1.0f);
    } else {
        const int tt = t - 1024;
        const int mt = tt >> 7;
        const int nx = tt & 127;
        gemm_fp16<0>(g_wvt + (size_t)mt * 128 * DD, DD,
                     g_xh + (size_t)nx * 128 * DD, DD,
                     g_vt + (size_t)mt * 128 * MS + nx * 128, MS,
                     DD, 1.0f);
    }
}

// Compact triangular grid: 136 tiles per batch (bi >= bj).
__global__ __launch_bounds__(NTHR, 2) void k_scores()
{
    const int t = blockIdx.x;
    int bi = (int)((sqrtf(8.f * t + 1.f) - 1.f) * 0.5f);
    while ((bi + 1) * (bi + 2) / 2 <= t) bi++;
    while (bi * (bi + 1) / 2 > t) bi--;
    const int bj = t - bi * (bi + 1) / 2;
    const int b = blockIdx.z;
    const int i0 = bi * 128, j0 = bj * 128;
    gemm_fp16<2>(g_th + (size_t)b * SS * DD + (size_t)i0 * DD, DD,
                 g_xh + (size_t)b * SS * DD + (size_t)j0 * DD, DD,
                 g_w + (size_t)b * SS * SS + (size_t)i0 * SS + j0, SS,
                 DD, 0.03125f, i0, j0, g_c + b * SS + j0);
}

__global__ __launch_bounds__(NTHR, 2) void k_out(float* __restrict__ out)
{
    const int b = blockIdx.z;
    const int my = (SS / 128 - 1) - blockIdx.y;   // big-K tiles first
    const int m0 = my * 128;
    gemm_fp16<1>(g_w + (size_t)b * SS * SS + (size_t)m0 * SS, SS,
                 g_vt + (size_t)blockIdx.x * 128 * MS + b * SS, MS,
                 out + (size_t)b * SS * DD + (size_t)m0 * DD + blockIdx.x * 128,
                 DD, m0 + 128, 1.0f);             // causal K truncation
}

// ---------------------------------------------------------------------------
// x fp32 -> fp16; first 16 blocks also zero g_c (colsum accumulators)
// ---------------------------------------------------------------------------
__global__ void k_cvtx(const float* __restrict__ x)
{
    if (blockIdx.x < 16) {
        const int zi = (blockIdx.x * 256 + threadIdx.x) * 4;
        *(float4*)(g_c + zi) = make_float4(0.f, 0.f, 0.f, 0.f);
    }
    const size_t i = ((size_t)blockIdx.x * 256 + threadIdx.x) * 4;
    float4 v = *(const float4*)(x + i);
    *(__half2*)(g_xh + i)     = __floats2half2_rn(v.x, v.y);
    *(__half2*)(g_xh + i + 2) = __floats2half2_rn(v.z, v.w);
}

// W convert: z=0 Wq straight, z=1 Wk straight, z=2 Wv transposed.
__global__ void k_cvtw(const float* __restrict__ Wq,
                       const float* __restrict__ Wk,
                       const float* __restrict__ Wv)
{
    const int z = blockIdx.z;
    const int tx = threadIdx.x, ty = threadIdx.y;   // 32 x 8
    const int x0 = blockIdx.x * 32, y0 = blockIdx.y * 32;
    if (z < 2) {
        const float* W = (z == 0) ? Wq : Wk;
        __half* O = (z == 0) ? g_wq16 : g_wk16;
#pragma unroll
        for (int i = 0; i < 32; i += 8) {
            const size_t idx = (size_t)(y0 + ty + i) * DD + x0 + tx;
            O[idx] = __float2half(W[idx]);
        }
    } else {
        __shared__ float t[32][33];
#pragma unroll
        for (int i = 0; i < 32; i += 8)
            t[ty + i][tx] = Wv[(size_t)(y0 + ty + i) * DD + x0 + tx];
        __syncthreads();
#pragma unroll
        for (int i = 0; i < 32; i += 8)
            g_wvt[(size_t)(x0 + ty + i) * DD + y0 + tx] =
                __float2half(t[tx][ty + i]);
    }
}

// vt[e][jg] *= 1/colsum[jg]  (recip fused; half2 x4 per thread)
__global__ void k_vscale()
{
    const size_t i2 = ((size_t)blockIdx.x * 256 + threadIdx.x) * 4;  // half2 idx
#pragma unroll
    for (int u = 0; u < 4; u++) {
        const size_t h2 = i2 + u;
        const int jg = (int)((h2 * 2) & (MS - 1));
        __half2 v = *(__half2*)(g_vt + h2 * 2);
        float2 f = __half22float2(v);
        f.x = __fdividef(f.x, g_c[jg]);
        f.y = __fdividef(f.y, g_c[jg + 1]);
        *(__half2*)(g_vt + h2 * 2) = __floats2half2_rn(f.x, f.y);
    }
}

// ---------------------------------------------------------------------------
extern "C" void kernel_launch(void* const* d_in, const int* in_sizes, int n_in,
                              void* d_out, int out_size)
{
    const float* x  = (const float*)d_in[0];
    const float* Wq = (const float*)d_in[1];
    const float* Wk = (const float*)d_in[2];
    const float* Wv = (const float*)d_in[3];
    float* out = (float*)d_out;

    cudaFuncSetAttribute(k_mt,     cudaFuncAttributeMaxDynamicSharedMemorySize, SMEM_BYTES);
    cudaFuncSetAttribute(k_proj,   cudaFuncAttributeMaxDynamicSharedMemorySize, SMEM_BYTES);
    cudaFuncSetAttribute(k_scores, cudaFuncAttributeMaxDynamicSharedMemorySize, SMEM_BYTES);
    cudaFuncSetAttribute(k_out,    cudaFuncAttributeMaxDynamicSharedMemorySize, SMEM_BYTES);

    dim3 tb(32, 8);

    // x -> fp16 (+ zero colsum accumulators)
    k_cvtx<<<MS * DD / 1024, 256>>>(x);

    // W converts: Wq, Wk straight; Wv transposed
    k_cvtw<<<dim3(32, 32, 3), tb>>>(Wq, Wk, Wv);

    // Mt = Wk Wq^T (64 tiles)
    k_mt<<<dim3(8, 8), NTHR, SMEM_BYTES>>>();

    // t = x Mt^T  +  v^T directly (2048 tiles total)
    k_proj<<<2048, NTHR, SMEM_BYTES>>>();

    // causal P = exp(t.x^T / 32), compact triangular grid, fused column sums
    k_scores<<<dim3(136, 1, BB), NTHR, SMEM_BYTES>>>();

    // fold 1/colsum into V^T columns (recip fused)
    k_vscale<<<(int)(((size_t)DD * MS / 2) / (256 * 4)), 256>>>();

    // out = P @ vt'
    k_out<<<dim3(DD / 128, SS / 128, BB), NTHR, SMEM_BYTES>>>(out);
}

// round 16
// speedup vs baseline: 1.1490x; 1.1490x over previous
#include <cuda_runtime.h>
#include <cuda_fp16.h>
#include <cstdint>

#define BB 8
#define SS 2048
#define DD 1024
#define MS (BB * SS)   // 16384

// ---------------- scratch (device globals; no cudaMalloc allowed) ----------
__device__ __half g_xh  [(size_t)MS * DD];      // 32 MB  x fp16
__device__ __half g_wq16[(size_t)DD * DD];      //  2 MB  Wq fp16 (row-major)
__device__ __half g_wk16[(size_t)DD * DD];      //  2 MB  Wk fp16 (row-major)
__device__ __half g_wvt [(size_t)DD * DD];      //  2 MB  Wv^T fp16
__device__ __half g_mt  [(size_t)DD * DD];      //  2 MB  (Wk Wq^T)[c][d] fp16
__device__ __half g_th  [(size_t)MS * DD];      // 32 MB  t = x (Wq Wk^T)
__device__ __half g_vt  [(size_t)DD * MS];      // 32 MB  v^T: [e][b*2048+j]
__device__ __half g_w   [(size_t)BB * SS * SS]; // 64 MB  P = exp(s/32) fp16
__device__ float  g_c   [(size_t)MS];           // 64 KB  column sums

// ---------------- smem: 2 stages x (A 16KB + B 16KB) -----------------------
#define STAGE_B 32768
#define SMEM_BYTES (2 * STAGE_B)   // 65536

// ---------------- PTX helpers ----------------------------------------------
__device__ __forceinline__ uint32_t smem_u32(const void* p) {
    uint32_t a;
    asm("{ .reg .u64 t; cvta.to.shared.u64 t, %1; cvt.u32.u64 %0, t; }"
        : "=r"(a) : "l"(p));
    return a;
}
__device__ __forceinline__ void cpa16(uint32_t d, const void* s) {
    asm volatile("cp.async.cg.shared.global [%0], [%1], 16;"
                 :: "r"(d), "l"(s) : "memory");
}
#define CP_COMMIT() asm volatile("cp.async.commit_group;" ::: "memory")
#define CP_WAIT(n)  asm volatile("cp.async.wait_group %0;" :: "n"(n) : "memory")

__device__ __forceinline__ void ldsm_x4(uint32_t* r, uint32_t addr) {
    asm volatile("ldmatrix.sync.aligned.m8n8.x4.shared.b16 {%0,%1,%2,%3}, [%4];"
        : "=r"(r[0]), "=r"(r[1]), "=r"(r[2]), "=r"(r[3]) : "r"(addr));
}
__device__ __forceinline__ void mma16816(float* c, const uint32_t* a,
                                         const uint32_t* b) {
    asm volatile(
        "mma.sync.aligned.m16n8k16.row.col.f32.f16.f16.f32 "
        "{%0,%1,%2,%3}, {%4,%5,%6,%7}, {%8,%9}, {%0,%1,%2,%3};"
        : "+f"(c[0]), "+f"(c[1]), "+f"(c[2]), "+f"(c[3])
        : "r"(a[0]), "r"(a[1]), "r"(a[2]), "r"(a[3]), "r"(b[0]), "r"(b[1]));
}

// fill one stage: A/B tiles 128 rows x 64 fp16 (128B/row), XOR swizzle
__device__ __forceinline__ void fill_stage(
    uint32_t sbase, int stg, const __half* A, int lda,
    const __half* B, int ldb, int k0, int tid)
{
    const uint32_t sA = sbase + stg * STAGE_B;
    const uint32_t sB = sA + 16384;
#pragma unroll
    for (int i = 0; i < 4; i++) {
        const int id = tid + (i << 8);
        const int r = id >> 3;
        const int c = id & 7;
        const uint32_t sw = (uint32_t)r * 128 + (uint32_t)((c ^ (r & 7)) << 4);
        cpa16(sA + sw, A + (size_t)r * lda + k0 + c * 8);
        cpa16(sB + sw, B + (size_t)r * ldb + k0 + c * 8);
    }
    CP_COMMIT();
}

// ---------------------------------------------------------------------------
// 128x128 tile GEMM (R14 core: 256 thr, 8 warps 2m x 4n, warp tile 64x32).
// C[m][n] = f(scale * sum_k A[m][k]*B[n][k]); kelems multiple of 64 (>=128).
// MODE 0: fp16 scaled; MODE 1: fp32 scaled;
// MODE 2: fp16 exp(scaled), causal-zeroed; fused column sums into gsum.
// ---------------------------------------------------------------------------
template<int MODE>
__device__ __forceinline__ void gemm_fp16(
    const __half* __restrict__ A, int lda,
    const __half* __restrict__ B, int ldb,
    void* __restrict__ Cv, int ldc, int kelems, float scale,
    int ri0 = 0, int cj0 = 0, float* gsum = nullptr)
{
    extern __shared__ char sm[];
    const uint32_t sbase = smem_u32(sm);
    const int tid  = threadIdx.x;
    const int lane = tid & 31;
    const int wid  = tid >> 5;
    const int wm   = (wid & 1) * 64;
    const int wn   = (wid >> 1) * 32;

    const int ra = lane & 15;
    const int ca = (lane >> 4) * 16;
    const int rb = (lane & 7) + (lane >> 4) * 8;
    const int cb = ((lane >> 3) & 1) * 16;

    float acc[4][4][4] = {};

    const int nc = kelems >> 6;
    fill_stage(sbase, 0, A, lda, B, ldb, 0, tid);

    for (int ch = 0; ch < nc; ch++) {
        const int s = ch & 1;
        if (ch + 1 < nc) {
            fill_stage(sbase, s ^ 1, A, lda, B, ldb, (ch + 1) << 6, tid);
            CP_WAIT(1);
        } else {
            CP_WAIT(0);
        }
        __syncthreads();

        const uint32_t sA = sbase + s * STAGE_B;
        const uint32_t sB = sA + 16384;
#pragma unroll
        for (int kk = 0; kk < 4; kk++) {
            uint32_t a[4][4], b[2][4];
#pragma unroll
            for (int mt = 0; mt < 4; mt++) {
                const int r = wm + mt * 16 + ra;
                const int col = kk * 32 + ca;
                ldsm_x4(a[mt], sA + (uint32_t)r * 128 +
                               (uint32_t)((((col >> 4) ^ (r & 7))) << 4));
            }
#pragma unroll
            for (int np = 0; np < 2; np++) {
                const int r = wn + np * 16 + rb;
                const int col = kk * 32 + cb;
                ldsm_x4(b[np], sB + (uint32_t)r * 128 +
                               (uint32_t)((((col >> 4) ^ (r & 7))) << 4));
            }
#pragma unroll
            for (int mt = 0; mt < 4; mt++)
#pragma unroll
                for (int nt = 0; nt < 4; nt++)
                    mma16816(acc[mt][nt], a[mt], &b[nt >> 1][(nt & 1) * 2]);
        }
        __syncthreads();
    }

    // epilogue
    const int er = lane >> 2;
    const int ec = (lane & 3) * 2;

    float* csum = (float*)sm;          // stages dead after final barrier
    if (MODE == 2) {
        if (tid < 128) csum[tid] = 0.f;
        __syncthreads();
    }
    float cs[4][2] = {};               // per-(nt) column partials (MODE 2)

#pragma unroll
    for (int mt = 0; mt < 4; mt++)
#pragma unroll
        for (int nt = 0; nt < 4; nt++) {
            const int r = wm + mt * 16 + er;
            const int cn = wn + nt * 8 + ec;
            if (MODE == 0) {
                __half* C = (__half*)Cv;
                *(__half2*)(C + (size_t)r * ldc + cn) =
                    __floats2half2_rn(acc[mt][nt][0] * scale,
                                      acc[mt][nt][1] * scale);
                *(__half2*)(C + (size_t)(r + 8) * ldc + cn) =
                    __floats2half2_rn(acc[mt][nt][2] * scale,
                                      acc[mt][nt][3] * scale);
            } else if (MODE == 1) {
                float* C = (float*)Cv;
                *(float2*)(C + (size_t)r * ldc + cn) =
                    make_float2(acc[mt][nt][0] * scale, acc[mt][nt][1] * scale);
                *(float2*)(C + (size_t)(r + 8) * ldc + cn) =
                    make_float2(acc[mt][nt][2] * scale, acc[mt][nt][3] * scale);
            } else {
                __half* C = (__half*)Cv;
                const int i0 = ri0 + r, i1 = ri0 + r + 8;
                const int j0c = cj0 + cn, j1c = cj0 + cn + 1;
                float e00 = (i0 >= j0c) ? __expf(acc[mt][nt][0] * scale) : 0.f;
                float e01 = (i0 >= j1c) ? __expf(acc[mt][nt][1] * scale) : 0.f;
                float e10 = (i1 >= j0c) ? __expf(acc[mt][nt][2] * scale) : 0.f;
                float e11 = (i1 >= j1c) ? __expf(acc[mt][nt][3] * scale) : 0.f;
                *(__half2*)(C + (size_t)r * ldc + cn) = __floats2half2_rn(e00, e01);
                *(__half2*)(C + (size_t)(r + 8) * ldc + cn) = __floats2half2_rn(e10, e11);
                cs[nt][0] += e00 + e10;
                cs[nt][1] += e01 + e11;
            }
        }

    if (MODE == 2) {
#pragma unroll
        for (int nt = 0; nt < 4; nt++) {
#pragma unroll
            for (int off = 16; off >= 4; off >>= 1) {
                cs[nt][0] += __shfl_down_sync(0xffffffffu, cs[nt][0], off);
                cs[nt][1] += __shfl_down_sync(0xffffffffu, cs[nt][1], off);
            }
            if (lane < 4) {
                const int c0 = wn + nt * 8 + lane * 2;
                atomicAdd(&csum[c0],     cs[nt][0]);
                atomicAdd(&csum[c0 + 1], cs[nt][1]);
            }
        }
        __syncthreads();
        if (tid < 128) atomicAdd(&gsum[tid], csum[tid]);
    }
}

// ---------------------------------------------------------------------------
// Mt[c][d] = sum_e Wk[c][e] * Wq[d][e]
// ---------------------------------------------------------------------------
__global__ __launch_bounds__(256, 2) void k_mt()
{
    gemm_fp16<0>(g_wk16 + (size_t)blockIdx.y * 128 * DD, DD,
                 g_wq16 + (size_t)blockIdx.x * 128 * DD, DD,
                 g_mt + (size_t)blockIdx.y * 128 * DD + blockIdx.x * 128, DD,
                 DD, 1.0f);
}

// ---------------------------------------------------------------------------
// Projections: t[i][c] = sum_d x[i][d] * Mt[c][d]  (tiles 0..1023)
//              vt[e][jg] = sum_d Wv^T[e][d] * x[jg][d]  (tiles 1024..2047)
// ---------------------------------------------------------------------------
__global__ __launch_bounds__(256, 2) void k_proj()
{
    const int t = blockIdx.x;
    if (t < 1024) {
        const int my = t >> 3;
        const int nx = t & 7;
        gemm_fp16<0>(g_xh + (size_t)my * 128 * DD, DD,
                     g_mt + (size_t)nx * 128 * DD, DD,
                     g_th + (size_t)my * 128 * DD + nx * 128, DD,
                     DD, 1.0f);
    } else {
        const int tt = t - 1024;
        const int mt = tt >> 7;
        const int nx = tt & 127;
        gemm_fp16<0>(g_wvt + (size_t)mt * 128 * DD, DD,
                     g_xh + (size_t)nx * 128 * DD, DD,
                     g_vt + (size_t)mt * 128 * MS + nx * 128, MS,
                     DD, 1.0f);
    }
}

// Compact triangular grid: 136 tiles per batch (bi >= bj).
__global__ __launch_bounds__(256, 2) void k_scores()
{
    const int t = blockIdx.x;
    int bi = (int)((sqrtf(8.f * t + 1.f) - 1.f) * 0.5f);
    while ((bi + 1) * (bi + 2) / 2 <= t) bi++;
    while (bi * (bi + 1) / 2 > t) bi--;
    const int bj = t - bi * (bi + 1) / 2;
    const int b = blockIdx.z;
    const int i0 = bi * 128, j0 = bj * 128;
    gemm_fp16<2>(g_th + (size_t)b * SS * DD + (size_t)i0 * DD, DD,
                 g_xh + (size_t)b * SS * DD + (size_t)j0 * DD, DD,
                 g_w + (size_t)b * SS * SS + (size_t)i0 * SS + j0, SS,
                 DD, 0.03125f, i0, j0, g_c + b * SS + j0);
}

__global__ __launch_bounds__(256, 2) void k_out(float* __restrict__ out)
{
    const int b = blockIdx.z;
    const int my = (SS / 128 - 1) - blockIdx.y;   // big-K tiles first
    const int m0 = my * 128;
    gemm_fp16<1>(g_w + (size_t)b * SS * SS + (size_t)m0 * SS, SS,
                 g_vt + (size_t)blockIdx.x * 128 * MS + b * SS, MS,
                 out + (size_t)b * SS * DD + (size_t)m0 * DD + blockIdx.x * 128,
                 DD, m0 + 128, 1.0f);             // causal K truncation
}

// ---------------------------------------------------------------------------
// Combined prep: t < 16384 -> x fp32->fp16 (first 16 blocks zero g_c);
// t >= 16384 -> W converts (z=0 Wq, z=1 Wk straight; z=2 Wv transposed).
// ---------------------------------------------------------------------------
__global__ void k_prep(const float* __restrict__ x,
                       const float* __restrict__ Wq,
                       const float* __restrict__ Wk,
                       const float* __restrict__ Wv)
{
    const int t = blockIdx.x;
    const int tid = threadIdx.x;
    if (t < 16384) {
        if (t < 16) {
            const int zi = (t * 256 + tid) * 4;
            *(float4*)(g_c + zi) = make_float4(0.f, 0.f, 0.f, 0.f);
        }
        const size_t i = ((size_t)t * 256 + tid) * 4;
        float4 v = *(const float4*)(x + i);
        *(__half2*)(g_xh + i)     = __floats2half2_rn(v.x, v.y);
        *(__half2*)(g_xh + i + 2) = __floats2half2_rn(v.z, v.w);
    } else {
        const int t2 = t - 16384;
        const int z = t2 >> 10;
        const int tile = t2 & 1023;
        const int x0 = (tile & 31) * 32;
        const int y0 = (tile >> 5) * 32;
        const int tx = tid & 31, ty = tid >> 5;   // 32 x 8
        if (z < 2) {
            const float* W = (z == 0) ? Wq : Wk;
            __half* O = (z == 0) ? g_wq16 : g_wk16;
#pragma unroll
            for (int i = 0; i < 32; i += 8) {
                const size_t idx = (size_t)(y0 + ty + i) * DD + x0 + tx;
                O[idx] = __float2half(W[idx]);
            }
        } else {
            __shared__ float tt[32][33];
#pragma unroll
            for (int i = 0; i < 32; i += 8)
                tt[ty + i][tx] = Wv[(size_t)(y0 + ty + i) * DD + x0 + tx];
            __syncthreads();
#pragma unroll
            for (int i = 0; i < 32; i += 8)
                g_wvt[(size_t)(x0 + ty + i) * DD + y0 + tx] =
                    __float2half(tt[tx][ty + i]);
        }
    }
}

// vt[e][jg] *= 1/colsum[jg]  (recip fused; half2 x4 per thread)
__global__ void k_vscale()
{
    const size_t i2 = ((size_t)blockIdx.x * 256 + threadIdx.x) * 4;  // half2 idx
#pragma unroll
    for (int u = 0; u < 4; u++) {
        const size_t h2 = i2 + u;
        const int jg = (int)((h2 * 2) & (MS - 1));
        __half2 v = *(__half2*)(g_vt + h2 * 2);
        float2 f = __half22float2(v);
        f.x = __fdividef(f.x, g_c[jg]);
        f.y = __fdividef(f.y, g_c[jg + 1]);
        *(__half2*)(g_vt + h2 * 2) = __floats2half2_rn(f.x, f.y);
    }
}

// ---------------------------------------------------------------------------
extern "C" void kernel_launch(void* const* d_in, const int* in_sizes, int n_in,
                              void* d_out, int out_size)
{
    const float* x  = (const float*)d_in[0];
    const float* Wq = (const float*)d_in[1];
    const float* Wk = (const float*)d_in[2];
    const float* Wv = (const float*)d_in[3];
    float* out = (float*)d_out;

    cudaFuncSetAttribute(k_mt,     cudaFuncAttributeMaxDynamicSharedMemorySize, SMEM_BYTES);
    cudaFuncSetAttribute(k_proj,   cudaFuncAttributeMaxDynamicSharedMemorySize, SMEM_BYTES);
    cudaFuncSetAttribute(k_scores, cudaFuncAttributeMaxDynamicSharedMemorySize, SMEM_BYTES);
    cudaFuncSetAttribute(k_out,    cudaFuncAttributeMaxDynamicSharedMemorySize, SMEM_BYTES);

    // x -> fp16 (+ zero colsums) and W converts, one launch
    k_prep<<<16384 + 3072, 256>>>(x, Wq, Wk, Wv);

    // Mt = Wk Wq^T (64 tiles)
    k_mt<<<dim3(8, 8), 256, SMEM_BYTES>>>();

    // t = x Mt^T  +  v^T directly (2048 tiles total)
    k_proj<<<2048, 256, SMEM_BYTES>>>();

    // causal P = exp(t.x^T / 32), compact triangular grid, fused column sums
    k_scores<<<dim3(136, 1, BB), 256, SMEM_BYTES>>>();

    // fold 1/colsum into V^T columns (recip fused)
    k_vscale<<<(int)(((size_t)DD * MS / 2) / (256 * 4)), 256>>>();

    // out = P @ vt' (big-K tiles first)
    k_out<<<dim3(DD / 128, SS / 128, BB), 256, SMEM_BYTES>>>(out);
}

// round 17
// speedup vs baseline: 1.1983x; 1.0429x over previous
#include <cuda_runtime.h>
#include <cuda_fp16.h>
#include <cstdint>

#define BB 8
#define SS 2048
#define DD 1024
#define MS (BB * SS)   // 16384

// ---------------- scratch (device globals; no cudaMalloc allowed) ----------
__device__ __half g_xh  [(size_t)MS * DD];      // 32 MB  x fp16
__device__ __half g_wq16[(size_t)DD * DD];      //  2 MB  Wq fp16 (row-major)
__device__ __half g_wk16[(size_t)DD * DD];      //  2 MB  Wk fp16 (row-major)
__device__ __half g_wvt [(size_t)DD * DD];      //  2 MB  Wv^T fp16
__device__ __half g_mt  [(size_t)DD * DD];      //  2 MB  (Wk Wq^T)[c][d] fp16
__device__ __half g_th  [(size_t)MS * DD];      // 32 MB  t = x (Wq Wk^T)
__device__ __half g_vt  [(size_t)DD * MS];      // 32 MB  v^T: [e][b*2048+j]
__device__ __half g_w   [(size_t)BB * SS * SS]; // 64 MB  P = exp(s/32) fp16
__device__ float  g_c   [(size_t)MS];           // 64 KB  column sums

// ---------------- smem: 2 stages x (A 16KB + B 16KB) -----------------------
#define STAGE_B 32768
#define SMEM_BYTES (2 * STAGE_B)   // 65536

// ---------------- PTX helpers ----------------------------------------------
__device__ __forceinline__ uint32_t smem_u32(const void* p) {
    uint32_t a;
    asm("{ .reg .u64 t; cvta.to.shared.u64 t, %1; cvt.u32.u64 %0, t; }"
        : "=r"(a) : "l"(p));
    return a;
}
__device__ __forceinline__ void cpa16(uint32_t d, const void* s) {
    asm volatile("cp.async.cg.shared.global [%0], [%1], 16;"
                 :: "r"(d), "l"(s) : "memory");
}
#define CP_COMMIT() asm volatile("cp.async.commit_group;" ::: "memory")
#define CP_WAIT(n)  asm volatile("cp.async.wait_group %0;" :: "n"(n) : "memory")

__device__ __forceinline__ void ldsm_x4(uint32_t* r, uint32_t addr) {
    asm volatile("ldmatrix.sync.aligned.m8n8.x4.shared.b16 {%0,%1,%2,%3}, [%4];"
        : "=r"(r[0]), "=r"(r[1]), "=r"(r[2]), "=r"(r[3]) : "r"(addr));
}
__device__ __forceinline__ void mma16816(float* c, const uint32_t* a,
                                         const uint32_t* b) {
    asm volatile(
        "mma.sync.aligned.m16n8k16.row.col.f32.f16.f16.f32 "
        "{%0,%1,%2,%3}, {%4,%5,%6,%7}, {%8,%9}, {%0,%1,%2,%3};"
        : "+f"(c[0]), "+f"(c[1]), "+f"(c[2]), "+f"(c[3])
        : "r"(a[0]), "r"(a[1]), "r"(a[2]), "r"(a[3]), "r"(b[0]), "r"(b[1]));
}

// fill one stage: A/B tiles 128 rows x 64 fp16 (128B/row), XOR swizzle
__device__ __forceinline__ void fill_stage(
    uint32_t sbase, int stg, const __half* A, int lda,
    const __half* B, int ldb, int k0, int tid)
{
    const uint32_t sA = sbase + stg * STAGE_B;
    const uint32_t sB = sA + 16384;
#pragma unroll
    for (int i = 0; i < 4; i++) {
        const int id = tid + (i << 8);
        const int r = id >> 3;
        const int c = id & 7;
        const uint32_t sw = (uint32_t)r * 128 + (uint32_t)((c ^ (r & 7)) << 4);
        cpa16(sA + sw, A + (size_t)r * lda + k0 + c * 8);
        cpa16(sB + sw, B + (size_t)r * ldb + k0 + c * 8);
    }
    CP_COMMIT();
}

// ---------------------------------------------------------------------------
// 128x128 tile GEMM (R14 core: 256 thr, 8 warps 2m x 4n, warp tile 64x32).
// C[m][n] = f(scale * sum_k A[m][k]*B[n][k]); kelems multiple of 64 (>=128).
// MODE 0: fp16 scaled; MODE 1: fp32 scaled;
// MODE 2: fp16 exp(scaled), causal-zeroed; fused column sums into gsum.
// ---------------------------------------------------------------------------
template<int MODE>
__device__ __forceinline__ void gemm_fp16(
    const __half* __restrict__ A, int lda,
    const __half* __restrict__ B, int ldb,
    void* __restrict__ Cv, int ldc, int kelems, float scale,
    int ri0 = 0, int cj0 = 0, float* gsum = nullptr)
{
    extern __shared__ char sm[];
    const uint32_t sbase = smem_u32(sm);
    const int tid  = threadIdx.x;
    const int lane = tid & 31;
    const int wid  = tid >> 5;
    const int wm   = (wid & 1) * 64;
    const int wn   = (wid >> 1) * 32;

    const int ra = lane & 15;
    const int ca = (lane >> 4) * 16;
    const int rb = (lane & 7) + (lane >> 4) * 8;
    const int cb = ((lane >> 3) & 1) * 16;

    float acc[4][4][4] = {};

    const int nc = kelems >> 6;
    fill_stage(sbase, 0, A, lda, B, ldb, 0, tid);

    for (int ch = 0; ch < nc; ch++) {
        const int s = ch & 1;
        if (ch + 1 < nc) {
            fill_stage(sbase, s ^ 1, A, lda, B, ldb, (ch + 1) << 6, tid);
            CP_WAIT(1);
        } else {
            CP_WAIT(0);
        }
        __syncthreads();

        const uint32_t sA = sbase + s * STAGE_B;
        const uint32_t sB = sA + 16384;
#pragma unroll
        for (int kk = 0; kk < 4; kk++) {
            uint32_t a[4][4], b[2][4];
#pragma unroll
            for (int mt = 0; mt < 4; mt++) {
                const int r = wm + mt * 16 + ra;
                const int col = kk * 32 + ca;
                ldsm_x4(a[mt], sA + (uint32_t)r * 128 +
                               (uint32_t)((((col >> 4) ^ (r & 7))) << 4));
            }
#pragma unroll
            for (int np = 0; np < 2; np++) {
                const int r = wn + np * 16 + rb;
                const int col = kk * 32 + cb;
                ldsm_x4(b[np], sB + (uint32_t)r * 128 +
                               (uint32_t)((((col >> 4) ^ (r & 7))) << 4));
            }
#pragma unroll
            for (int mt = 0; mt < 4; mt++)
#pragma unroll
                for (int nt = 0; nt < 4; nt++)
                    mma16816(acc[mt][nt], a[mt], &b[nt >> 1][(nt & 1) * 2]);
        }
        __syncthreads();
    }

    // epilogue
    const int er = lane >> 2;
    const int ec = (lane & 3) * 2;

    float* csum = (float*)sm;          // stages dead after final barrier
    if (MODE == 2) {
        if (tid < 128) csum[tid] = 0.f;
        __syncthreads();
    }
    float cs[4][2] = {};               // per-(nt) column partials (MODE 2)

#pragma unroll
    for (int mt = 0; mt < 4; mt++)
#pragma unroll
        for (int nt = 0; nt < 4; nt++) {
            const int r = wm + mt * 16 + er;
            const int cn = wn + nt * 8 + ec;
            if (MODE == 0) {
                __half* C = (__half*)Cv;
                *(__half2*)(C + (size_t)r * ldc + cn) =
                    __floats2half2_rn(acc[mt][nt][0] * scale,
                                      acc[mt][nt][1] * scale);
                *(__half2*)(C + (size_t)(r + 8) * ldc + cn) =
                    __floats2half2_rn(acc[mt][nt][2] * scale,
                                      acc[mt][nt][3] * scale);
            } else if (MODE == 1) {
                float* C = (float*)Cv;
                *(float2*)(C + (size_t)r * ldc + cn) =
                    make_float2(acc[mt][nt][0] * scale, acc[mt][nt][1] * scale);
                *(float2*)(C + (size_t)(r + 8) * ldc + cn) =
                    make_float2(acc[mt][nt][2] * scale, acc[mt][nt][3] * scale);
            } else {
                __half* C = (__half*)Cv;
                const int i0 = ri0 + r, i1 = ri0 + r + 8;
                const int j0c = cj0 + cn, j1c = cj0 + cn + 1;
                float e00 = (i0 >= j0c) ? __expf(acc[mt][nt][0] * scale) : 0.f;
                float e01 = (i0 >= j1c) ? __expf(acc[mt][nt][1] * scale) : 0.f;
                float e10 = (i1 >= j0c) ? __expf(acc[mt][nt][2] * scale) : 0.f;
                float e11 = (i1 >= j1c) ? __expf(acc[mt][nt][3] * scale) : 0.f;
                *(__half2*)(C + (size_t)r * ldc + cn) = __floats2half2_rn(e00, e01);
                *(__half2*)(C + (size_t)(r + 8) * ldc + cn) = __floats2half2_rn(e10, e11);
                cs[nt][0] += e00 + e10;
                cs[nt][1] += e01 + e11;
            }
        }

    if (MODE == 2) {
#pragma unroll
        for (int nt = 0; nt < 4; nt++) {
#pragma unroll
            for (int off = 16; off >= 4; off >>= 1) {
                cs[nt][0] += __shfl_down_sync(0xffffffffu, cs[nt][0], off);
                cs[nt][1] += __shfl_down_sync(0xffffffffu, cs[nt][1], off);
            }
            if (lane < 4) {
                const int c0 = wn + nt * 8 + lane * 2;
                atomicAdd(&csum[c0],     cs[nt][0]);
                atomicAdd(&csum[c0 + 1], cs[nt][1]);
            }
        }
        __syncthreads();
        if (tid < 128) atomicAdd(&gsum[tid], csum[tid]);
    }
}

// ---------------------------------------------------------------------------
// Mt[c][d] = sum_e Wk[c][e] * Wq[d][e]
// ---------------------------------------------------------------------------
__global__ __launch_bounds__(256, 2) void k_mt()
{
    gemm_fp16<0>(g_wk16 + (size_t)blockIdx.y * 128 * DD, DD,
                 g_wq16 + (size_t)blockIdx.x * 128 * DD, DD,
                 g_mt + (size_t)blockIdx.y * 128 * DD + blockIdx.x * 128, DD,
                 DD, 1.0f);
}

// ---------------------------------------------------------------------------
// t-projection only: t[i][c] = sum_d x[i][d] * Mt[c][d]  (1024 tiles)
// ---------------------------------------------------------------------------
__global__ __launch_bounds__(256, 2) void k_proj_t()
{
    const int t = blockIdx.x;
    const int my = t >> 3;
    const int nx = t & 7;
    gemm_fp16<0>(g_xh + (size_t)my * 128 * DD, DD,
                 g_mt + (size_t)nx * 128 * DD, DD,
                 g_th + (size_t)my * 128 * DD + nx * 128, DD,
                 DD, 1.0f);
}

// ---------------------------------------------------------------------------
// Combined scores + vt-projection (independent; backfills scores tail waves).
// Blocks 0..1087: causal P = exp(t.x^T/32), compact triangular per batch,
//                 fused column sums.
// Blocks 1088..2111: vt[e][jg] = sum_d Wv^T[e][d] * x[jg][d].
// ---------------------------------------------------------------------------
__global__ __launch_bounds__(256, 2) void k_sv()
{
    const int t = blockIdx.x;
    if (t < 1088) {
        const int b = t / 136;
        const int tt = t - b * 136;
        int bi = (int)((sqrtf(8.f * tt + 1.f) - 1.f) * 0.5f);
        while ((bi + 1) * (bi + 2) / 2 <= tt) bi++;
        while (bi * (bi + 1) / 2 > tt) bi--;
        const int bj = tt - bi * (bi + 1) / 2;
        const int i0 = bi * 128, j0 = bj * 128;
        gemm_fp16<2>(g_th + (size_t)b * SS * DD + (size_t)i0 * DD, DD,
                     g_xh + (size_t)b * SS * DD + (size_t)j0 * DD, DD,
                     g_w + (size_t)b * SS * SS + (size_t)i0 * SS + j0, SS,
                     DD, 0.03125f, i0, j0, g_c + b * SS + j0);
    } else {
        const int tt = t - 1088;
        const int mt = tt >> 7;                  // e-tile 0..7
        const int nx = tt & 127;                 // jg-tile 0..127
        gemm_fp16<0>(g_wvt + (size_t)mt * 128 * DD, DD,
                     g_xh + (size_t)nx * 128 * DD, DD,
                     g_vt + (size_t)mt * 128 * MS + nx * 128, MS,
                     DD, 1.0f);
    }
}

__global__ __launch_bounds__(256, 2) void k_out(float* __restrict__ out)
{
    const int b = blockIdx.z;
    const int my = (SS / 128 - 1) - blockIdx.y;   // big-K tiles first
    const int m0 = my * 128;
    gemm_fp16<1>(g_w + (size_t)b * SS * SS + (size_t)m0 * SS, SS,
                 g_vt + (size_t)blockIdx.x * 128 * MS + b * SS, MS,
                 out + (size_t)b * SS * DD + (size_t)m0 * DD + blockIdx.x * 128,
                 DD, m0 + 128, 1.0f);             // causal K truncation
}

// ---------------------------------------------------------------------------
// Combined prep: t < 16384 -> x fp32->fp16 (first 16 blocks zero g_c);
// t >= 16384 -> W converts (z=0 Wq, z=1 Wk straight; z=2 Wv transposed).
// ---------------------------------------------------------------------------
__global__ void k_prep(const float* __restrict__ x,
                       const float* __restrict__ Wq,
                       const float* __restrict__ Wk,
                       const float* __restrict__ Wv)
{
    const int t = blockIdx.x;
    const int tid = threadIdx.x;
    if (t < 16384) {
        if (t < 16) {
            const int zi = (t * 256 + tid) * 4;
            *(float4*)(g_c + zi) = make_float4(0.f, 0.f, 0.f, 0.f);
        }
        const size_t i = ((size_t)t * 256 + tid) * 4;
        float4 v = *(const float4*)(x + i);
        *(__half2*)(g_xh + i)     = __floats2half2_rn(v.x, v.y);
        *(__half2*)(g_xh + i + 2) = __floats2half2_rn(v.z, v.w);
    } else {
        const int t2 = t - 16384;
        const int z = t2 >> 10;
        const int tile = t2 & 1023;
        const int x0 = (tile & 31) * 32;
        const int y0 = (tile >> 5) * 32;
        const int tx = tid & 31, ty = tid >> 5;   // 32 x 8
        if (z < 2) {
            const float* W = (z == 0) ? Wq : Wk;
            __half* O = (z == 0) ? g_wq16 : g_wk16;
#pragma unroll
            for (int i = 0; i < 32; i += 8) {
                const size_t idx = (size_t)(y0 + ty + i) * DD + x0 + tx;
                O[idx] = __float2half(W[idx]);
            }
        } else {
            __shared__ float tt[32][33];
#pragma unroll
            for (int i = 0; i < 32; i += 8)
                tt[ty + i][tx] = Wv[(size_t)(y0 + ty + i) * DD + x0 + tx];
            __syncthreads();
#pragma unroll
            for (int i = 0; i < 32; i += 8)
                g_wvt[(size_t)(x0 + ty + i) * DD + y0 + tx] =
                    __float2half(tt[tx][ty + i]);
        }
    }
}

// vt[e][jg] *= 1/colsum[jg]  (recip fused; half2 x4 per thread)
__global__ void k_vscale()
{
    const size_t i2 = ((size_t)blockIdx.x * 256 + threadIdx.x) * 4;  // half2 idx
#pragma unroll
    for (int u = 0; u < 4; u++) {
        const size_t h2 = i2 + u;
        const int jg = (int)((h2 * 2) & (MS - 1));
        __half2 v = *(__half2*)(g_vt + h2 * 2);
        float2 f = __half22float2(v);
        f.x = __fdividef(f.x, g_c[jg]);
        f.y = __fdividef(f.y, g_c[jg + 1]);
        *(__half2*)(g_vt + h2 * 2) = __floats2half2_rn(f.x, f.y);
    }
}

// ---------------------------------------------------------------------------
extern "C" void kernel_launch(void* const* d_in, const int* in_sizes, int n_in,
                              void* d_out, int out_size)
{
    const float* x  = (const float*)d_in[0];
    const float* Wq = (const float*)d_in[1];
    const float* Wk = (const float*)d_in[2];
    const float* Wv = (const float*)d_in[3];
    float* out = (float*)d_out;

    cudaFuncSetAttribute(k_mt,     cudaFuncAttributeMaxDynamicSharedMemorySize, SMEM_BYTES);
    cudaFuncSetAttribute(k_proj_t, cudaFuncAttributeMaxDynamicSharedMemorySize, SMEM_BYTES);
    cudaFuncSetAttribute(k_sv,     cudaFuncAttributeMaxDynamicSharedMemorySize, SMEM_BYTES);
    cudaFuncSetAttribute(k_out,    cudaFuncAttributeMaxDynamicSharedMemorySize, SMEM_BYTES);

    // x -> fp16 (+ zero colsums) and W converts, one launch
    k_prep<<<16384 + 3072, 256>>>(x, Wq, Wk, Wv);

    // Mt = Wk Wq^T (64 tiles)
    k_mt<<<dim3(8, 8), 256, SMEM_BYTES>>>();

    // t = x Mt^T (1024 tiles)
    k_proj_t<<<1024, 256, SMEM_BYTES>>>();

    // scores (P = exp, fused colsums) + vt projection, one launch (2112 blocks)
    k_sv<<<2112, 256, SMEM_BYTES>>>();

    // fold 1/colsum into V^T columns (recip fused)
    k_vscale<<<(int)(((size_t)DD * MS / 2) / (256 * 4)), 256>>>();

    // out = P @ vt' (big-K tiles first)
    k_out<<<dim3(DD / 128, SS / 128, BB), 256, SMEM_BYTES>>>(out);
}